// round 5
// baseline (speedup 1.0000x reference)
#include <cuda_runtime.h>
#include <cstdint>

// Problem constants (fixed shapes from setup_inputs)
#define BB 64
#define CC 3
#define HH 224
#define WW 224
#define CW (CC * WW)          // 672
#define NN 224                // Gram size
#define RP 112                // rows per cluster CTA (NN/2)
#define TAIL 45               // 224 - int(0.8*224)
#define NSWEEP 9              // cap; early-exit may trigger sooner
#define THR 1e-12f            // relative skip threshold (cos^2)

// Scratch (device globals: allocation-free per harness rules)
__device__ float g_A[BB * HH * CW];     // masked, scaled input  [b][h][cw]
__device__ float g_G[BB * NN * NN];     // Gram A A^T per image
__device__ float g_Ut[BB * TAIL * NN];  // tail eigenvectors, row t = u_t^T
__device__ int   g_cnt[BB];             // observed-entry counts

// ---------------------------------------------------------------------------
// K1: A = (2x-1)*mask in [B,H,CW] layout; per-image mask count via atomics.
// ---------------------------------------------------------------------------
__global__ void build_kernel(const float* __restrict__ x,
                             const int* __restrict__ mask) {
    int idx = blockIdx.x * 256 + threadIdx.x;
    int b   = idx / (HH * CW);
    int rem = idx - b * (HH * CW);
    int h   = rem / CW;
    int cw  = rem - h * CW;
    int c   = cw / WW;
    int w   = cw - c * WW;

    int m = mask[idx];
    float xv = x[((b * CC + c) * HH + h) * WW + w];
    g_A[idx] = m ? (2.0f * xv - 1.0f) : 0.0f;

    int s = m;
    #pragma unroll
    for (int o = 16; o; o >>= 1) s += __shfl_xor_sync(0xffffffffu, s, o);
    __shared__ int ss[8];
    int warp = threadIdx.x >> 5, lane = threadIdx.x & 31;
    if (lane == 0) ss[warp] = s;
    __syncthreads();
    if (threadIdx.x == 0) {
        int t = 0;
        #pragma unroll
        for (int i = 0; i < 8; i++) t += ss[i];
        atomicAdd(&g_cnt[b], t);
    }
}

// ---------------------------------------------------------------------------
// K2: G = A A^T per image. grid (7,7,BB), block (16,16), 2x2 micro-tile.
// ---------------------------------------------------------------------------
__global__ void gram_kernel() {
    __shared__ float As[32][33];
    __shared__ float Bs[32][33];
    int b  = blockIdx.z;
    int i0 = blockIdx.y * 32, j0 = blockIdx.x * 32;
    const float* Ab = g_A + (size_t)b * HH * CW;
    int tx = threadIdx.x, ty = threadIdx.y;
    int t = ty * 16 + tx;

    float a00 = 0.f, a01 = 0.f, a10 = 0.f, a11 = 0.f;
    for (int k0 = 0; k0 < CW; k0 += 32) {
        #pragma unroll
        for (int q = 0; q < 4; q++) {
            int e = t + q * 256;
            int rr = e >> 5, kk = e & 31;
            As[rr][kk] = Ab[(i0 + rr) * CW + k0 + kk];
            Bs[rr][kk] = Ab[(j0 + rr) * CW + k0 + kk];
        }
        __syncthreads();
        #pragma unroll
        for (int kk = 0; kk < 32; kk++) {
            float x0 = As[2 * ty][kk], x1 = As[2 * ty + 1][kk];
            float y0 = Bs[2 * tx][kk], y1 = Bs[2 * tx + 1][kk];
            a00 += x0 * y0; a01 += x0 * y1;
            a10 += x1 * y0; a11 += x1 * y1;
        }
        __syncthreads();
    }
    float* Gb = g_G + (size_t)b * NN * NN;
    Gb[(i0 + 2 * ty    ) * NN + j0 + 2 * tx    ] = a00;
    Gb[(i0 + 2 * ty    ) * NN + j0 + 2 * tx + 1] = a01;
    Gb[(i0 + 2 * ty + 1) * NN + j0 + 2 * tx    ] = a10;
    Gb[(i0 + 2 * ty + 1) * NN + j0 + 2 * tx + 1] = a11;
}

// ---------------------------------------------------------------------------
// K3: one-sided Jacobi, row-split across a 2-CTA cluster.
// CTA r of cluster holds rows [r*112, r*112+112) of all 224 columns.
// Per round: phase1 partial dots -> exchange via DSMEM -> cluster barrier ->
// phase2 full pp, identical rotation scalars in both CTAs, local rotate.
// Tournament pairing: round r pairs (223, r) and ((r+p)%223, (r-p)%223).
// ---------------------------------------------------------------------------
__device__ __forceinline__ void pair_ij(int r, int p, int& i, int& j) {
    if (p == 0) { i = NN - 1; j = r; }
    else {
        i = r + p; if (i >= NN - 1) i -= (NN - 1);
        j = r - p; if (j < 0)       j += (NN - 1);
    }
}

__device__ __forceinline__ void st_peer_f32(const float* lptr, float v,
                                            unsigned peer) {
    uint32_t laddr = (uint32_t)__cvta_generic_to_shared(lptr);
    uint32_t raddr;
    asm("mapa.shared::cluster.u32 %0, %1, %2;"
        : "=r"(raddr) : "r"(laddr), "r"(peer));
    asm volatile("st.shared::cluster.f32 [%0], %1;"
                 :: "r"(raddr), "f"(v) : "memory");
}

__device__ __forceinline__ void cluster_bar() {
    asm volatile("barrier.cluster.arrive.aligned;" ::: "memory");
    asm volatile("barrier.cluster.wait.aligned;"   ::: "memory");
}

__global__ void __launch_bounds__(1024, 1) __cluster_dims__(2, 1, 1)
jacobi_kernel() {
    extern __shared__ float sm[];
    float* W    = sm;                     // 224 cols x 112 local rows
    float* nrm  = W + NN * RP;            // 224 replicated squared norms
    float* part = nrm + NN;               // [2 parity][2 srcrank][112]
    float* nbuf = part + 2 * 2 * RP;      // [2 srcrank][224] init-norm exchange
    int*   rnk  = (int*)(nbuf + 2 * NN);  // 224 ranks
    __shared__ int rot_flag;

    int b    = blockIdx.x >> 1;
    unsigned rank = blockIdx.x & 1u;
    unsigned peer = rank ^ 1u;
    int tid = threadIdx.x, warp = tid >> 5, lane = tid & 31;
    const float* Gb = g_G + (size_t)b * NN * NN;

    // load local row-slice of G (columns of G = rows, symmetric)
    for (int i = tid; i < NN * RP; i += 1024) {
        int col = i / RP, rr = i - col * RP;
        W[i] = Gb[col * NN + (int)rank * RP + rr];
    }
    __syncthreads();

    // initial column norms: partial over local rows, exchange, combine
    #pragma unroll
    for (int k = 0; k < 7; k++) {
        int col = warp + 32 * k;
        const float* cc = W + col * RP;
        float s = 0.f;
        #pragma unroll
        for (int m = 0; m < 4; m++) {
            int rr = lane + 32 * m;
            float v = (rr < RP) ? cc[rr] : 0.f;
            s += v * v;
        }
        #pragma unroll
        for (int o = 16; o; o >>= 1) s += __shfl_xor_sync(0xffffffffu, s, o);
        if (lane == 0) {
            nbuf[rank * NN + col] = s;
            st_peer_f32(&nbuf[rank * NN + col], s, peer);
        }
    }
    cluster_bar();
    if (tid < NN) nrm[tid] = nbuf[tid] + nbuf[NN + tid];
    __syncthreads();

    for (int sw = 0; sw < NSWEEP; ++sw) {
        if (tid == 0) rot_flag = 0;
        __syncthreads();
        for (int r = 0; r < NN - 1; ++r) {
            int par = r & 1;
            float* pbuf = part + par * 2 * RP;

            // ---- phase 1: partial dots over local 112 rows ----
            #pragma unroll
            for (int q = 0; q < 4; ++q) {
                int p = warp + (q << 5);
                if (p < RP) {                     // warp-uniform
                    int i, j; pair_ij(r, p, i, j);
                    const float* ci = W + i * RP;
                    const float* cj = W + j * RP;
                    float pp = 0.f;
                    #pragma unroll
                    for (int m = 0; m < 4; m++) {
                        int rr = lane + 32 * m;
                        float a = (rr < RP) ? ci[rr] : 0.f;
                        float d = (rr < RP) ? cj[rr] : 0.f;
                        pp += a * d;
                    }
                    #pragma unroll
                    for (int o = 16; o; o >>= 1)
                        pp += __shfl_xor_sync(0xffffffffu, pp, o);
                    if (lane == 0) {
                        pbuf[rank * RP + p] = pp;
                        st_peer_f32(&pbuf[rank * RP + p], pp, peer);
                    }
                }
            }
            cluster_bar();

            // ---- phase 2: full pp, rotate local halves ----
            #pragma unroll
            for (int q = 0; q < 4; ++q) {
                int p = warp + (q << 5);
                if (p < RP) {
                    int i, j; pair_ij(r, p, i, j);
                    float pp = pbuf[p] + pbuf[RP + p];   // fixed order: det.
                    float qi = nrm[i], qj = nrm[j];
                    if (pp * pp > THR * qi * qj) {
                        if (lane == 0) rot_flag = 1;
                        float tau = (qj - qi) / (2.0f * pp);
                        float tt = 1.0f / (fabsf(tau) + sqrtf(1.0f + tau * tau));
                        if (tau < 0.f) tt = -tt;
                        float c = rsqrtf(1.0f + tt * tt);
                        float s = c * tt;
                        float* ci = W + i * RP;
                        float* cj = W + j * RP;
                        #pragma unroll
                        for (int m = 0; m < 4; m++) {
                            int rr = lane + 32 * m;
                            if (rr < RP) {
                                float a = ci[rr], d = cj[rr];
                                ci[rr] = c * a - s * d;
                                cj[rr] = s * a + c * d;
                            }
                        }
                        if (lane == 0) {
                            float c2 = c * c, s2 = s * s, cs2 = 2.f * c * s;
                            nrm[i] = c2 * qi - cs2 * pp + s2 * qj;
                            nrm[j] = s2 * qi + cs2 * pp + c2 * qj;
                        }
                    }
                }
            }
            __syncthreads();   // local: rotations visible to next round
        }
        if (rot_flag == 0) break;     // identical decision in both CTAs
        __syncthreads();
    }

    // rank of each column (0 = smallest norm), deterministic tie-break
    if (tid < NN) {
        float mine = nrm[tid];
        int rk = 0;
        for (int j = 0; j < NN; j++) {
            float o = nrm[j];
            rk += (o < mine) || (o == mine && j < tid);
        }
        rnk[tid] = rk;
    }
    __syncthreads();

    // write normalized tail eigenvector slices (local 112 rows of each)
    for (int i = tid; i < NN * RP; i += 1024) {
        int t = i / RP, rr = i - t * RP;
        int rk = rnk[t];
        if (rk < TAIL)
            g_Ut[((size_t)b * TAIL + rk) * NN + (int)rank * RP + rr] =
                W[i] * rsqrtf(nrm[t]);
    }
    cluster_bar();   // no CTA exits while peer may still use cluster state
}

// ---------------------------------------------------------------------------
// K4: R = A - Ut (Ut^T A); epilogue: /p_obs, clip, (r+1)/2, scatter to NCHW.
// Two CTAs per image (336 columns each), T in 45 registers/thread.
// ---------------------------------------------------------------------------
__global__ void __launch_bounds__(336, 2) recon_kernel(float* __restrict__ out) {
    __shared__ __align__(16) float sU[TAIL * NN];
    int b = blockIdx.x >> 1, half = blockIdx.x & 1;
    int tid = threadIdx.x;
    int cw  = half * 336 + tid;
    const float* Ub = g_Ut + (size_t)b * TAIL * NN;
    for (int i = tid; i < TAIL * NN; i += 336) sU[i] = Ub[i];
    __syncthreads();

    const float* Ab = g_A + (size_t)b * HH * CW;
    float inv_p = (float)(HH * CW) / (float)g_cnt[b];

    float acc[TAIL];
    #pragma unroll
    for (int t = 0; t < TAIL; t++) acc[t] = 0.f;

    for (int h = 0; h < HH; h += 4) {
        float a0 = Ab[(h + 0) * CW + cw];
        float a1 = Ab[(h + 1) * CW + cw];
        float a2 = Ab[(h + 2) * CW + cw];
        float a3 = Ab[(h + 3) * CW + cw];
        #pragma unroll
        for (int t = 0; t < TAIL; t++) {
            float4 u = *(const float4*)&sU[t * NN + h];
            acc[t] += u.x * a0 + u.y * a1 + u.z * a2 + u.w * a3;
        }
    }

    int c = cw / WW, w = cw - c * WW;
    float* ob = out + (((size_t)b * CC + c) * HH) * WW + w;

    for (int h = 0; h < HH; h += 4) {
        float a0 = Ab[(h + 0) * CW + cw];
        float a1 = Ab[(h + 1) * CW + cw];
        float a2 = Ab[(h + 2) * CW + cw];
        float a3 = Ab[(h + 3) * CW + cw];
        float s0 = 0.f, s1 = 0.f, s2 = 0.f, s3 = 0.f;
        #pragma unroll
        for (int t = 0; t < TAIL; t++) {
            float4 u = *(const float4*)&sU[t * NN + h];
            float tv = acc[t];
            s0 += u.x * tv; s1 += u.y * tv; s2 += u.z * tv; s3 += u.w * tv;
        }
        float r0 = (a0 - s0) * inv_p;
        float r1 = (a1 - s1) * inv_p;
        float r2 = (a2 - s2) * inv_p;
        float r3 = (a3 - s3) * inv_p;
        r0 = fminf(1.f, fmaxf(-1.f, r0));
        r1 = fminf(1.f, fmaxf(-1.f, r1));
        r2 = fminf(1.f, fmaxf(-1.f, r2));
        r3 = fminf(1.f, fmaxf(-1.f, r3));
        ob[(h + 0) * WW] = 0.5f * r0 + 0.5f;
        ob[(h + 1) * WW] = 0.5f * r1 + 0.5f;
        ob[(h + 2) * WW] = 0.5f * r2 + 0.5f;
        ob[(h + 3) * WW] = 0.5f * r3 + 0.5f;
    }
}

// ---------------------------------------------------------------------------
extern "C" void kernel_launch(void* const* d_in, const int* in_sizes, int n_in,
                              void* d_out, int out_size) {
    const float* x    = (const float*)d_in[0];
    const int*   mask = (const int*)d_in[1];
    float*       out  = (float*)d_out;

    // W + nrm + part(dbl) + nbuf + rnk
    const int JAC_SMEM = (NN * RP + NN + 2 * 2 * RP + 2 * NN) * (int)sizeof(float)
                       + NN * (int)sizeof(int);

    void* cntp = nullptr;
    cudaGetSymbolAddress(&cntp, g_cnt);
    cudaMemsetAsync(cntp, 0, BB * sizeof(int));

    cudaFuncSetAttribute(jacobi_kernel,
                         cudaFuncAttributeMaxDynamicSharedMemorySize, JAC_SMEM);

    build_kernel<<<BB * HH * CW / 256, 256>>>(x, mask);
    gram_kernel<<<dim3(7, 7, BB), dim3(16, 16)>>>();
    jacobi_kernel<<<2 * BB, 1024, JAC_SMEM>>>();
    recon_kernel<<<2 * BB, 336>>>(out);
}